// round 14
// baseline (speedup 1.0000x reference)
#include <cuda_runtime.h>
#include <cuda_fp16.h>

// ===========================================================================
// B=16, N=1024, D=512, H=8, dk=64. ROWS=16384.
// HMMA (mma.sync m16n8k16), fp32 accum, split-fp16 where precision needs it:
//   QK proj: fused 3-term (Xh*Wh + Xl*Wh + Xh*Wl) with SHARED staged tiles
//   S      : 2-term (Qh*Kh + Ql*Kh); flash with register-resident softmax
//   V proj : 1-term, out proj: 1-term, PV: V-hi only
// hgemm: 128 threads, 64x64 warp tiles. hgemm_qk3: K-chunk 32, 4 shared tiles.
// ===========================================================================
#define ROWS 16384
#define PADK 72
#define TILEB (128 * PADK * 2)
#define GEMM_SMEM (4 * TILEB)

// QK3 kernel: K-chunk 32, stride 40 halfs
#define PAD2 40
#define TIL2 (128 * PAD2 * 2)          // 10240 B
#define QK3_STAGE (4 * TIL2)           // 40960 B (Xh|Xl|Wh|Wl)
#define QK3_SMEM (2 * QK3_STAGE)       // 81920 B

#define XSTR  ((long long)ROWS * 512)
#define WSTR  (524288LL)
#define QKSTR ((long long)ROWS * 1024)
#define HSTR  ((long long)ROWS * 1024)
#define OSTR  ((long long)ROWS * 512)

// Flash smem layout (bytes): Qh 18432 | Ql 18432 | 2 x (Kh 9216 + V 18432)
#define NKT    16
#define OFF_Q  0
#define OFF_KV 36864
#define KVBUF  27648
#define FA_SMEM 92160

// ---------------------------------------------------------------------------
// Static device scratch
// ---------------------------------------------------------------------------
__device__ __half g_Wqkh[2][524288], g_Wqkl[2][524288];
__device__ __half g_Wvh [2][524288];
__device__ __half g_Woh [2][524288];
__device__ __half g_Xh  [2][8388608], g_Xl[2][8388608];
__device__ __half g_QKh [2][16777216], g_QKl[2][16777216];
__device__ __half g_Vth [2][16777216];
__device__ __half g_H   [2][16777216];

// ---------------------------------------------------------------------------
// PTX helpers
// ---------------------------------------------------------------------------
__device__ __forceinline__ unsigned smem_u32(const void* p) {
    unsigned a;
    asm("{ .reg .u64 t; cvta.to.shared.u64 t, %1; cvt.u32.u64 %0, t; }"
        : "=r"(a) : "l"(p));
    return a;
}
__device__ __forceinline__ void cpasync16(unsigned s, const void* g) {
    asm volatile("cp.async.cg.shared.global [%0], [%1], 16;" :: "r"(s), "l"(g));
}
__device__ __forceinline__ void cp_commit() {
    asm volatile("cp.async.commit_group;" ::: "memory");
}
__device__ __forceinline__ void cp_wait0() {
    asm volatile("cp.async.wait_group 0;" ::: "memory");
}
__device__ __forceinline__ void ldm4(unsigned& r0, unsigned& r1, unsigned& r2,
                                     unsigned& r3, unsigned a) {
    asm volatile("ldmatrix.sync.aligned.m8n8.x4.shared.b16 {%0,%1,%2,%3}, [%4];"
                 : "=r"(r0), "=r"(r1), "=r"(r2), "=r"(r3) : "r"(a));
}
__device__ __forceinline__ void mma16816(float* c, const unsigned* a,
                                         const unsigned* b) {
    asm volatile(
        "mma.sync.aligned.m16n8k16.row.col.f32.f16.f16.f32 "
        "{%0,%1,%2,%3}, {%4,%5,%6,%7}, {%8,%9}, {%0,%1,%2,%3};"
        : "+f"(c[0]), "+f"(c[1]), "+f"(c[2]), "+f"(c[3])
        : "r"(a[0]), "r"(a[1]), "r"(a[2]), "r"(a[3]), "r"(b[0]), "r"(b[1]));
}
__device__ __forceinline__ void split2(float v0, float v1, __half2& hi, __half2& lo) {
    __half h0 = __float2half_rn(v0), h1 = __float2half_rn(v1);
    __half l0 = __float2half_rn(v0 - __half2float(h0));
    __half l1 = __float2half_rn(v1 - __half2float(h1));
    hi = __halves2half2(h0, h1);
    lo = __halves2half2(l0, l1);
}
__device__ __forceinline__ unsigned h2bits(float a, float b) {
    __half2 t = __floats2half2_rn(a, b);
    return *reinterpret_cast<unsigned*>(&t);
}

// ---------------------------------------------------------------------------
// Fused 3-term QK projection: C = Xh*Wh^T + Xl*Wh^T + Xh*Wl^T (pair out).
// 128 threads, 4 warps of 64x64. K-chunk 32 (2 ks), 4 tiles staged per chunk.
// Per ks: 16 ldm4 -> 96 MMAs. blockIdx.z = stream.
// ---------------------------------------------------------------------------
__global__ __launch_bounds__(128, 2)
void hgemm_qk3(const __half* __restrict__ Xh_, const __half* __restrict__ Xl_,
               const __half* __restrict__ Wh_, const __half* __restrict__ Wl_,
               __half* __restrict__ Ch_, __half* __restrict__ Cl_) {
    extern __shared__ __align__(16) char smem[];
    const unsigned sbase = smem_u32(smem);

    const int tid = threadIdx.x;
    const int wid = tid >> 5, lane = tid & 31;
    const int wm = wid & 1, wn = wid >> 1;
    const int zb = (int)blockIdx.z;

    const long long aoff = (long long)zb * XSTR + (long long)(blockIdx.y * 128) * 512;
    const long long boff = (long long)zb * WSTR + (long long)(blockIdx.x * 128) * 512;
    const __half* Ah = Xh_ + aoff;
    const __half* Al = Xl_ + aoff;
    const __half* Bh = Wh_ + boff;
    const __half* Bl = Wl_ + boff;

    // loader: 512 x 16B chunks per tile, 4 per thread per tile
    int lr[4], ls[4];
    unsigned lso[4];
#pragma unroll
    for (int i = 0; i < 4; i++) {
        int c = tid + i * 128;
        lr[i] = c >> 2;
        ls[i] = (c & 3) * 8;
        lso[i] = (unsigned)(lr[i] * PAD2 + ls[i]) * 2;
    }

#define QK3_LOAD(g, bf)                                                       \
    do {                                                                      \
        unsigned sl = sbase + (bf) * QK3_STAGE;                               \
        _Pragma("unroll")                                                     \
        for (int i_ = 0; i_ < 4; i_++) {                                      \
            long long go = (long long)lr[i_] * 512 + (g) * 32 + ls[i_];       \
            cpasync16(sl + lso[i_],            Ah + go);                      \
            cpasync16(sl + TIL2 + lso[i_],     Al + go);                      \
            cpasync16(sl + 2 * TIL2 + lso[i_], Bh + go);                      \
            cpasync16(sl + 3 * TIL2 + lso[i_], Bl + go);                      \
        }                                                                     \
        cp_commit();                                                          \
    } while (0)

    QK3_LOAD(0, 0);

    float acc[4][8][4];
#pragma unroll
    for (int i = 0; i < 4; i++)
#pragma unroll
        for (int j = 0; j < 8; j++)
#pragma unroll
            for (int k = 0; k < 4; k++) acc[i][j][k] = 0.f;

    const int sub = lane >> 3, r8 = lane & 7;

    for (int g = 0; g < 16; g++) {
        const int bf = g & 1;
        cp_wait0();
        __syncthreads();
        if (g + 1 < 16) QK3_LOAD(g + 1, bf ^ 1);

        const unsigned sl = sbase + bf * QK3_STAGE;
#pragma unroll
        for (int ks = 0; ks < 2; ks++) {
            const int k0 = ks * 16;
            unsigned ah[4][4], al[4][4];
#pragma unroll
            for (int mi = 0; mi < 4; mi++) {
                unsigned off = (unsigned)((wm * 64 + mi * 16 + r8 + (sub & 1) * 8) * PAD2 +
                                          k0 + (sub >> 1) * 8) * 2;
                ldm4(ah[mi][0], ah[mi][1], ah[mi][2], ah[mi][3], sl + off);
                ldm4(al[mi][0], al[mi][1], al[mi][2], al[mi][3], sl + TIL2 + off);
            }
            // B in two 32-col halves to cap register liveness
#pragma unroll
            for (int nh = 0; nh < 2; nh++) {
                unsigned bh[4][2], bl[4][2];
#pragma unroll
                for (int np = 0; np < 2; np++) {
                    unsigned off = (unsigned)((wn * 64 + nh * 32 + np * 16 + r8 +
                                               (sub >> 1) * 8) * PAD2 +
                                              k0 + (sub & 1) * 8) * 2;
                    unsigned q0, q1, q2, q3;
                    ldm4(q0, q1, q2, q3, sl + 2 * TIL2 + off);
                    bh[np * 2][0] = q0; bh[np * 2][1] = q1;
                    bh[np * 2 + 1][0] = q2; bh[np * 2 + 1][1] = q3;
                    ldm4(q0, q1, q2, q3, sl + 3 * TIL2 + off);
                    bl[np * 2][0] = q0; bl[np * 2][1] = q1;
                    bl[np * 2 + 1][0] = q2; bl[np * 2 + 1][1] = q3;
                }
#pragma unroll
                for (int mi = 0; mi < 4; mi++)
#pragma unroll
                    for (int ni = 0; ni < 4; ni++) {
                        float* ac = acc[mi][nh * 4 + ni];
                        mma16816(ac, ah[mi], bh[ni]);
                        mma16816(ac, al[mi], bh[ni]);
                        mma16816(ac, ah[mi], bl[ni]);
                    }
            }
        }
        __syncthreads();
    }
#undef QK3_LOAD

    // pair epilogue -> Ch/Cl
    const int trow = lane >> 2, tcol = (lane & 3) * 2;
    const long long coff = (long long)zb * QKSTR;
    __half* Ch = Ch_ + coff;
    __half* Cl = Cl_ + coff;
#pragma unroll
    for (int mi = 0; mi < 4; mi++) {
#pragma unroll
        for (int ni = 0; ni < 8; ni++) {
            int rg = blockIdx.y * 128 + wm * 64 + mi * 16 + trow;
            int cg = blockIdx.x * 128 + wn * 64 + ni * 8 + tcol;
            float* ac = acc[mi][ni];
            __half2 h, l;
            size_t o0 = (size_t)rg * 1024 + cg;
            size_t o1 = (size_t)(rg + 8) * 1024 + cg;
            split2(ac[0], ac[1], h, l);
            *(__half2*)(Ch + o0) = h;
            *(__half2*)(Cl + o0) = l;
            split2(ac[2], ac[3], h, l);
            *(__half2*)(Ch + o1) = h;
            *(__half2*)(Cl + o1) = l;
        }
    }
}

// ---------------------------------------------------------------------------
// Multi-term HMMA GEMM (R13-proven): 128 threads, 64x64 warp tiles.
// modes: 1 fp32 | 7 fp16 + V row remap (halfoff*zb).
// ---------------------------------------------------------------------------
__global__ __launch_bounds__(128, 3)
void hgemm(const __half* __restrict__ A0, const __half* __restrict__ A1,
           const __half* __restrict__ A2,
           long long sAh, long long sAb, int lda,
           const __half* __restrict__ B0, const __half* __restrict__ B1,
           const __half* __restrict__ B2,
           long long sBh, long long sBb, int ldb,
           void* __restrict__ C0, void* __restrict__ C1,
           long long sCh, long long sCb, int ldc,
           int Kper, int nterm, int mode, int halfoff) {
    extern __shared__ __align__(16) char smem[];
    const unsigned smA = smem_u32(smem);
    const unsigned smB = smA + 2 * TILEB;

    const int tid = threadIdx.x;
    const int wid = tid >> 5, lane = tid & 31;
    const int wm = wid & 1, wn = wid >> 1;

    const int zh = (int)(blockIdx.z >> 4), zb = (int)(blockIdx.z & 15);
    const long long aoff = sAh * zh + sAb * zb + (long long)(blockIdx.y * 128) * lda;
    const long long boff = sBh * zh + sBb * zb + (long long)(blockIdx.x * 128) * ldb;
    const __half* At[3] = {A0 + aoff, A1 ? A1 + aoff : A0, A2 ? A2 + aoff : A0};
    const __half* Bt[3] = {B0 + boff, B1 ? B1 + boff : B0, B2 ? B2 + boff : B0};

    const int r0 = tid >> 3, s0 = tid & 7;
    const unsigned sbase0 = (unsigned)(r0 * PADK + s0 * 8) * 2;
    const int ta0 = r0 * lda + s0 * 8, tb0 = r0 * ldb + s0 * 8;

    const int T = Kper >> 6;
    const int TT = nterm * T;

#define LOAD_TILE(g, bf)                                                      \
    do {                                                                      \
        int t_ = ((g) >= T) + ((g) >= 2 * T);                                 \
        int kk_ = (g) - t_ * T;                                               \
        const __half* ap = At[t_] + kk_ * 64;                                 \
        const __half* bp = Bt[t_] + kk_ * 64;                                 \
        unsigned sa = smA + (bf) * TILEB;                                     \
        unsigned sbm = smB + (bf) * TILEB;                                    \
        _Pragma("unroll")                                                     \
        for (int i_ = 0; i_ < 8; i_++) {                                      \
            cpasync16(sa + sbase0 + (unsigned)(i_ * 16 * PADK) * 2,           \
                      ap + ta0 + i_ * 16 * lda);                              \
            cpasync16(sbm + sbase0 + (unsigned)(i_ * 16 * PADK) * 2,          \
                      bp + tb0 + i_ * 16 * ldb);                              \
        }                                                                     \
        cp_commit();                                                          \
    } while (0)

    LOAD_TILE(0, 0);

    float acc[4][8][4];
#pragma unroll
    for (int i = 0; i < 4; i++)
#pragma unroll
        for (int j = 0; j < 8; j++)
#pragma unroll
            for (int k = 0; k < 4; k++) acc[i][j][k] = 0.f;

    const int sub = lane >> 3, r8 = lane & 7;

    for (int g = 0; g < TT; g++) {
        const int bf = g & 1;
        cp_wait0();
        __syncthreads();
        if (g + 1 < TT) LOAD_TILE(g + 1, bf ^ 1);

        const unsigned ab = smA + bf * TILEB;
        const unsigned bb = smB + bf * TILEB;
#pragma unroll
        for (int ks = 0; ks < 4; ks++) {
            const int k0 = ks * 16;
            unsigned a[4][4];
#pragma unroll
            for (int mi = 0; mi < 4; mi++) {
                int mrow = wm * 64 + mi * 16 + r8 + (sub & 1) * 8;
                int mcol = k0 + (sub >> 1) * 8;
                ldm4(a[mi][0], a[mi][1], a[mi][2], a[mi][3],
                     ab + (unsigned)(mrow * PADK + mcol) * 2);
            }
#pragma unroll
            for (int nh = 0; nh < 2; nh++) {
                unsigned b[4][2];
#pragma unroll
                for (int np = 0; np < 2; np++) {
                    int nrow = wn * 64 + nh * 32 + np * 16 + r8 + (sub >> 1) * 8;
                    int kcol = k0 + (sub & 1) * 8;
                    unsigned q0, q1, q2, q3;
                    ldm4(q0, q1, q2, q3, bb + (unsigned)(nrow * PADK + kcol) * 2);
                    b[np * 2][0] = q0; b[np * 2][1] = q1;
                    b[np * 2 + 1][0] = q2; b[np * 2 + 1][1] = q3;
                }
#pragma unroll
                for (int mi = 0; mi < 4; mi++)
#pragma unroll
                    for (int ni = 0; ni < 4; ni++)
                        mma16816(acc[mi][nh * 4 + ni], a[mi], b[ni]);
            }
        }
        __syncthreads();
    }
#undef LOAD_TILE

    const int trow = lane >> 2, tcol = (lane & 3) * 2;
    const long long coff = sCh * zh + sCb * zb;

#pragma unroll
    for (int mi = 0; mi < 4; mi++) {
#pragma unroll
        for (int ni = 0; ni < 8; ni++) {
            int rg = blockIdx.y * 128 + wm * 64 + mi * 16 + trow;
            int cg = blockIdx.x * 128 + wn * 64 + ni * 8 + tcol;
            float* ac = acc[mi][ni];
            if (mode == 1) {
                float* p0 = (float*)C0 + coff + (size_t)rg * ldc + cg;
                float* p1 = (float*)C0 + coff + (size_t)(rg + 8) * ldc + cg;
                *(float2*)p0 = make_float2(ac[0], ac[1]);
                *(float2*)p1 = make_float2(ac[2], ac[3]);
            } else {  // mode 7: single fp16 out + V row remap (halfoff * zb)
                int ho = halfoff * zb;
                int ra = ((rg >> 6) << 7) + (rg & 63) + ho;
                int rb0 = rg + 8;
                int rb = ((rb0 >> 6) << 7) + (rb0 & 63) + ho;
                *(__half2*)((__half*)C0 + (size_t)ra * ldc + cg) =
                    __floats2half2_rn(ac[0], ac[1]);
                *(__half2*)((__half*)C0 + (size_t)rb * ldc + cg) =
                    __floats2half2_rn(ac[2], ac[3]);
            }
        }
    }
}

// ---------------------------------------------------------------------------
// Flash attention, FA2-style register softmax (R12-proven, unchanged).
// ---------------------------------------------------------------------------
__global__ __launch_bounds__(256, 1)
void flash_attn(const __half* __restrict__ QKhB, const __half* __restrict__ QKlB,
                const __half* __restrict__ VhB,
                __half* __restrict__ H0B, __half* __restrict__ H1B) {
    extern __shared__ __align__(16) char smem[];
    const unsigned sb = smem_u32(smem);

    const int tid = threadIdx.x, wid = tid >> 5, lane = tid & 31;
    const int sub = lane >> 3, r8 = lane & 7;
    const int trow = lane >> 2, tq2 = (lane & 3) * 2;
    const int qt = blockIdx.x, z = blockIdx.y;
    const int h = z >> 4, b = z & 15;
    const int s = blockIdx.z;

    const __half* QKh = QKhB + (size_t)s * QKSTR;
    const __half* QKl = QKlB + (size_t)s * QKSTR;
    const __half* Vh  = VhB  + (size_t)s * 16777216;
    __half* C0 = H0B + s * 64;
    __half* C1 = H1B + s * 64;

    {
        const size_t rbase = (size_t)(b << 10) + qt * 128;
#pragma unroll
        for (int i = 0; i < 4; i++) {
            int c = tid + i * 256;
            int r = c >> 3, sc = c & 7;
            unsigned sof = (unsigned)(r * PADK + sc * 8) * 2;
            size_t go = (rbase + r) * 1024 + h * 64 + sc * 8;
            cpasync16(sb + OFF_Q + sof, QKh + go);
            cpasync16(sb + OFF_Q + 18432 + sof, QKl + go);
        }
    }

#define LOAD_KV(kt, bi)                                                       \
    do {                                                                      \
        unsigned kb = sb + OFF_KV + (bi) * KVBUF;                             \
        _Pragma("unroll")                                                     \
        for (int i_ = 0; i_ < 2; i_++) {                                      \
            int c_ = tid + i_ * 256;                                          \
            int r_ = c_ >> 3, sc_ = c_ & 7;                                   \
            cpasync16(kb + (unsigned)(r_ * PADK + sc_ * 8) * 2,               \
                      QKh + ((size_t)(b << 10) + (kt) * 64 + r_) * 1024 +     \
                          512 + h * 64 + sc_ * 8);                            \
        }                                                                     \
        _Pragma("unroll")                                                     \
        for (int i_ = 0; i_ < 4; i_++) {                                      \
            int c_ = tid + i_ * 256;                                          \
            int r_ = c_ >> 3, sc_ = c_ & 7;                                   \
            cpasync16(kb + 9216 + (unsigned)(r_ * PADK + sc_ * 8) * 2,        \
                      Vh + (size_t)(h * 128 + r_) * 16384 +                   \
                          (size_t)(b << 10) + (kt) * 64 + sc_ * 8);           \
        }                                                                     \
        cp_commit();                                                          \
    } while (0)

    LOAD_KV(0, 0);
    cp_wait0();

    float O[16][4];
#pragma unroll
    for (int i = 0; i < 16; i++)
#pragma unroll
        for (int j = 0; j < 4; j++) O[i][j] = 0.f;
    float m0 = -1e30f, m1 = -1e30f, l0 = 0.f, l1 = 0.f;

    for (int kt = 0; kt < NKT; kt++) {
        const int bi = kt & 1;
        if (kt) cp_wait0();
        __syncthreads();
        if (kt + 1 < NKT) LOAD_KV(kt + 1, bi ^ 1);

        const unsigned Kb = sb + OFF_KV + bi * KVBUF;
        const unsigned Vb = Kb + 9216;

        float sc[8][4];
#pragma unroll
        for (int t = 0; t < 8; t++)
#pragma unroll
            for (int j = 0; j < 4; j++) sc[t][j] = 0.f;

#pragma unroll
        for (int ks = 0; ks < 4; ks++) {
            const int k0 = ks * 16;
            unsigned ah[4], al[4];
            unsigned offa = (unsigned)((wid * 16 + r8 + (sub & 1) * 8) * PADK +
                                       k0 + (sub >> 1) * 8) * 2;
            ldm4(ah[0], ah[1], ah[2], ah[3], sb + OFF_Q + offa);
            ldm4(al[0], al[1], al[2], al[3], sb + OFF_Q + 18432 + offa);
            unsigned bk[8][2];
#pragma unroll
            for (int nb = 0; nb < 4; nb++) {
                unsigned offb = (unsigned)((nb * 16 + r8 + (sub >> 1) * 8) * PADK +
                                           k0 + (sub & 1) * 8) * 2;
                unsigned q0, q1, q2, q3;
                ldm4(q0, q1, q2, q3, Kb + offb);
                bk[2 * nb][0] = q0; bk[2 * nb][1] = q1;
                bk[2 * nb + 1][0] = q2; bk[2 * nb + 1][1] = q3;
            }
#pragma unroll
            for (int t = 0; t < 8; t++) {
                mma16816(sc[t], ah, bk[t]);
                mma16816(sc[t], al, bk[t]);
            }
        }

        float mt0 = sc[0][0], mt1 = sc[0][2];
#pragma unroll
        for (int t = 0; t < 8; t++) {
            mt0 = fmaxf(mt0, fmaxf(sc[t][0], sc[t][1]));
            mt1 = fmaxf(mt1, fmaxf(sc[t][2], sc[t][3]));
        }
        mt0 = fmaxf(mt0, __shfl_xor_sync(~0u, mt0, 1));
        mt0 = fmaxf(mt0, __shfl_xor_sync(~0u, mt0, 2));
        mt1 = fmaxf(mt1, __shfl_xor_sync(~0u, mt1, 1));
        mt1 = fmaxf(mt1, __shfl_xor_sync(~0u, mt1, 2));
        float mn0 = fmaxf(m0, mt0), mn1 = fmaxf(m1, mt1);
        float f0 = __expf(m0 - mn0), f1 = __expf(m1 - mn1);
        float sum0 = 0.f, sum1 = 0.f;
        unsigned pf[4][4];
#pragma unroll
        for (int kk = 0; kk < 4; kk++) {
            float e00 = __expf(sc[2 * kk][0] - mn0);
            float e01 = __expf(sc[2 * kk][1] - mn0);
            float e02 = __expf(sc[2 * kk][2] - mn1);
            float e03 = __expf(sc[2 * kk][3] - mn1);
            float e10 = __expf(sc[2 * kk + 1][0] - mn0);
            float e11 = __expf(sc[2 * kk + 1][1] - mn0);
            float e12 = __expf(sc[2 * kk + 1][2] - mn1);
            float e13 = __expf(sc[2 * kk + 1][3] - mn1);
            sum0 += e00 + e01 + e10 + e11;
            sum1 += e02 + e03 + e12 + e13;
            pf[kk][0] = h2bits(e00, e01);
            pf[kk][1] = h2bits(e02, e03);
            pf[kk][2] = h2bits(e10, e11);
            pf[kk][3] = h2bits(e12, e13);
        }
        sum0 += __shfl_xor_sync(~0u, sum0, 1);
        sum0 += __shfl_xor_sync(~0u, sum0, 2);
        sum1 += __shfl_xor_sync(~0u, sum1, 1);
        sum1 += __shfl_xor_sync(~0u, sum1, 2);
        l0 = l0 * f0 + sum0;  m0 = mn0;
        l1 = l1 * f1 + sum1;  m1 = mn1;

#pragma unroll
        for (int ni = 0; ni < 16; ni++) {
            O[ni][0] *= f0; O[ni][1] *= f0;
            O[ni][2] *= f1; O[ni][3] *= f1;
        }
#pragma unroll
        for (int kk = 0; kk < 4; kk++) {
            const int k0 = kk * 16;
            unsigned bv[16][2];
#pragma unroll
            for (int nb = 0; nb < 8; nb++) {
                unsigned offv = (unsigned)((nb * 16 + r8 + (sub >> 1) * 8) * PADK +
                                           k0 + (sub & 1) * 8) * 2;
                unsigned q0, q1, q2, q3;
                ldm4(q0, q1, q2, q3, Vb + offv);
                bv[2 * nb][0] = q0; bv[2 * nb][1] = q1;
                bv[2 * nb + 1][0] = q2; bv[2 * nb + 1][1] = q3;
            }
#pragma unroll
            for (int ni = 0; ni < 16; ni++)
                mma16816(O[ni], pf[kk], bv[ni]);
        }
    }
#undef LOAD_KV

    const float inv0 = 1.f / l0, inv1 = 1.f / l1;
    const long long coff = 128LL * h + 1048576LL * b;
    const int rg0 = qt * 128 + wid * 16 + trow, rg1 = rg0 + 8;
#pragma unroll
    for (int ni = 0; ni < 16; ni++) {
        int cg = ni * 8 + tq2;
        __half* base = (cg < 64) ? C0 : C1;
        int cl = cg & 63;
        *(__half2*)(base + coff + (size_t)rg0 * 1024 + cl) =
            __floats2half2_rn(O[ni][0] * inv0, O[ni][1] * inv0);
        *(__half2*)(base + coff + (size_t)rg1 * 1024 + cl) =
            __floats2half2_rn(O[ni][2] * inv1, O[ni][3] * inv1);
    }
}

// ---------------------------------------------------------------------------
// Fused weight prep + input conversion (unchanged)
// ---------------------------------------------------------------------------
__global__ void prep_w(const float* __restrict__ Wqn, const float* __restrict__ Wkn,
                       const float* __restrict__ Wqp, const float* __restrict__ Wkp,
                       const float* __restrict__ Wvn, const float* __restrict__ Wvp,
                       const float* __restrict__ Won, const float* __restrict__ Wop,
                       __half* __restrict__ Wqkh, __half* __restrict__ Wqkl,
                       __half* __restrict__ Wvh, __half* __restrict__ Woh) {
    int idx = blockIdx.x * blockDim.x + threadIdx.x;
    if (idx >= 524288) return;
    int task = blockIdx.y;
    int st = task & 1;
    if (task < 2) {
        const float* Wq = st ? Wqp : Wqn;
        const float* Wk = st ? Wkp : Wkn;
        int j = idx >> 9, d = idx & 511;
        int jj = j & 511;
        float v;
        if (j < 512)
            v = Wq[((size_t)((jj >> 6) * 512 + d)) * 64 + (jj & 63)] * 0.125f;
        else
            v = Wk[((size_t)((jj >> 6) * 512 + d)) * 64 + (jj & 63)];
        __half h = __float2half_rn(v);
        Wqkh[(size_t)st * WSTR + idx] = h;
        Wqkl[(size_t)st * WSTR + idx] = __float2half_rn(v - __half2float(h));
    } else if (task < 4) {
        const float* Wv = st ? Wvp : Wvn;
        int j = idx >> 9, d = idx & 511;
        Wvh[(size_t)st * WSTR + idx] =
            __float2half_rn(Wv[((size_t)((j >> 6) * 512 + d)) * 64 + (j & 63)]);
    } else {
        const float* Wo = st ? Wop : Won;
        int e = idx >> 10, j = idx & 1023;
        Woh[(size_t)st * WSTR + idx] = __float2half_rn(Wo[(size_t)j * 512 + e]);
    }
}

__global__ void cvt_pair(const float* __restrict__ Xn, const float* __restrict__ Xp,
                         __half* __restrict__ Yh, __half* __restrict__ Yl) {
    int i = blockIdx.x * blockDim.x + threadIdx.x;
    if (i >= ROWS * 512 / 4) return;
    int st = blockIdx.y;
    const float* X = st ? Xp : Xn;
    float4 v = ((const float4*)X)[i];
    __half2 h0, l0, h1, l1;
    split2(v.x, v.y, h0, l0);
    split2(v.z, v.w, h1, l1);
    uint2 uh, ul;
    uh.x = *reinterpret_cast<unsigned*>(&h0);
    uh.y = *reinterpret_cast<unsigned*>(&h1);
    ul.x = *reinterpret_cast<unsigned*>(&l0);
    ul.y = *reinterpret_cast<unsigned*>(&l1);
    ((uint2*)(Yh + (size_t)st * XSTR))[i] = uh;
    ((uint2*)(Yl + (size_t)st * XSTR))[i] = ul;
}

// ---------------------------------------------------------------------------
// Host launcher: 6 kernel launches
// ---------------------------------------------------------------------------
extern "C" void kernel_launch(void* const* d_in, const int* in_sizes, int n_in,
                              void* d_out, int out_size) {
    const float* Xn  = (const float*)d_in[0];
    const float* Xp  = (const float*)d_in[1];
    const float* Wqn = (const float*)d_in[2];
    const float* Wqp = (const float*)d_in[3];
    const float* Wkn = (const float*)d_in[4];
    const float* Wkp = (const float*)d_in[5];
    const float* Wvn = (const float*)d_in[6];
    const float* Wvp = (const float*)d_in[7];
    const float* Won = (const float*)d_in[8];
    const float* Wop = (const float*)d_in[9];
    float* out = (float*)d_out;

    __half *Wqkh, *Wqkl, *Wvh, *Woh, *Xh, *Xl, *QKh, *QKl, *Vth, *H;
    cudaGetSymbolAddress((void**)&Wqkh, g_Wqkh);
    cudaGetSymbolAddress((void**)&Wqkl, g_Wqkl);
    cudaGetSymbolAddress((void**)&Wvh,  g_Wvh);
    cudaGetSymbolAddress((void**)&Woh,  g_Woh);
    cudaGetSymbolAddress((void**)&Xh,   g_Xh);
    cudaGetSymbolAddress((void**)&Xl,   g_Xl);
    cudaGetSymbolAddress((void**)&QKh,  g_QKh);
    cudaGetSymbolAddress((void**)&QKl,  g_QKl);
    cudaGetSymbolAddress((void**)&Vth,  g_Vth);
    cudaGetSymbolAddress((void**)&H,    g_H);

    cudaFuncSetAttribute(hgemm, cudaFuncAttributeMaxDynamicSharedMemorySize,
                         GEMM_SMEM);
    cudaFuncSetAttribute(hgemm_qk3, cudaFuncAttributeMaxDynamicSharedMemorySize,
                         QK3_SMEM);
    cudaFuncSetAttribute(flash_attn, cudaFuncAttributeMaxDynamicSharedMemorySize,
                         FA_SMEM);

    // 1) fused weight prep + input conversion
    prep_w<<<dim3(2048, 6), 256>>>(Wqn, Wkn, Wqp, Wkp, Wvn, Wvp, Won, Wop,
                                   Wqkh, Wqkl, Wvh, Woh);
    cvt_pair<<<dim3(8192, 2), 256>>>(Xn, Xp, Xh, Xl);

    // 2) Q,K projections: fused 3-term with shared tiles, both streams (z)
    hgemm_qk3<<<dim3(8, 128, 2), 128, QK3_SMEM>>>(Xh, Xl, Wqkh, Wqkl, QKh, QKl);

    // 3) V transposed, 1-term, mode 7 (remap, halfoff = 64*z), both streams
    hgemm<<<dim3(128, 8, 2), 128, GEMM_SMEM>>>(
        Wvh, nullptr, nullptr, 0, WSTR, 512,
        Xh, nullptr, nullptr, 0, XSTR, 512,
        Vth, nullptr, 0, 0, ROWS, 512, 1, 7, 64);

    // 4) flash attention (FA2 register softmax), both streams (z)
    flash_attn<<<dim3(8, 128, 2), 256, FA_SMEM>>>(
        QKh, QKl, Vth, H, H + QKSTR);

    // 5) output projections, 1-term, fp32 out, both streams (z)
    hgemm<<<dim3(4, 128, 2), 128, GEMM_SMEM>>>(
        H, nullptr, nullptr, 0, HSTR, 1024,
        Woh, nullptr, nullptr, 0, WSTR, 1024,
        out, nullptr, 0, OSTR, 512, 1024, 1, 1, 0);
}

// round 15
// speedup vs baseline: 1.0333x; 1.0333x over previous
#include <cuda_runtime.h>
#include <cuda_fp16.h>

// ===========================================================================
// B=16, N=1024, D=512, H=8, dk=64. ROWS=16384.
// HMMA (mma.sync m16n8k16), fp32 accum, split-fp16 where precision needs it:
//   QK proj: 3-term (Xh*Wh + Xl*Wh + Xh*Wl), pair out
//   S      : 2-term (Qh*Kh + Ql*Kh); flash with register-resident softmax
//   V proj : 1-term, out proj: 1-term, PV: V-hi only
// 4 launches: prep_all | hgemm23 (QK+V fused grid) | flash | out-proj.
// ===========================================================================
#define ROWS 16384
#define PADK 72
#define TILEB (128 * PADK * 2)
#define GEMM_SMEM (4 * TILEB)

#define XSTR  ((long long)ROWS * 512)
#define WSTR  (524288LL)
#define QKSTR ((long long)ROWS * 1024)
#define HSTR  ((long long)ROWS * 1024)
#define OSTR  ((long long)ROWS * 512)

// Flash smem layout (bytes): Qh 18432 | Ql 18432 | 2 x (Kh 9216 + V 18432)
#define NKT    16
#define OFF_Q  0
#define OFF_KV 36864
#define KVBUF  27648
#define FA_SMEM 92160

// ---------------------------------------------------------------------------
// Static device scratch
// ---------------------------------------------------------------------------
__device__ __half g_Wqkh[2][524288], g_Wqkl[2][524288];
__device__ __half g_Wvh [2][524288];
__device__ __half g_Woh [2][524288];
__device__ __half g_Xh  [2][8388608], g_Xl[2][8388608];
__device__ __half g_QKh [2][16777216], g_QKl[2][16777216];
__device__ __half g_Vth [2][16777216];
__device__ __half g_H   [2][16777216];

// ---------------------------------------------------------------------------
// PTX helpers
// ---------------------------------------------------------------------------
__device__ __forceinline__ unsigned smem_u32(const void* p) {
    unsigned a;
    asm("{ .reg .u64 t; cvta.to.shared.u64 t, %1; cvt.u32.u64 %0, t; }"
        : "=r"(a) : "l"(p));
    return a;
}
__device__ __forceinline__ void cpasync16(unsigned s, const void* g) {
    asm volatile("cp.async.cg.shared.global [%0], [%1], 16;" :: "r"(s), "l"(g));
}
__device__ __forceinline__ void cp_commit() {
    asm volatile("cp.async.commit_group;" ::: "memory");
}
__device__ __forceinline__ void cp_wait0() {
    asm volatile("cp.async.wait_group 0;" ::: "memory");
}
__device__ __forceinline__ void ldm4(unsigned& r0, unsigned& r1, unsigned& r2,
                                     unsigned& r3, unsigned a) {
    asm volatile("ldmatrix.sync.aligned.m8n8.x4.shared.b16 {%0,%1,%2,%3}, [%4];"
                 : "=r"(r0), "=r"(r1), "=r"(r2), "=r"(r3) : "r"(a));
}
__device__ __forceinline__ void mma16816(float* c, const unsigned* a,
                                         const unsigned* b) {
    asm volatile(
        "mma.sync.aligned.m16n8k16.row.col.f32.f16.f16.f32 "
        "{%0,%1,%2,%3}, {%4,%5,%6,%7}, {%8,%9}, {%0,%1,%2,%3};"
        : "+f"(c[0]), "+f"(c[1]), "+f"(c[2]), "+f"(c[3])
        : "r"(a[0]), "r"(a[1]), "r"(a[2]), "r"(a[3]), "r"(b[0]), "r"(b[1]));
}
__device__ __forceinline__ void split2(float v0, float v1, __half2& hi, __half2& lo) {
    __half h0 = __float2half_rn(v0), h1 = __float2half_rn(v1);
    __half l0 = __float2half_rn(v0 - __half2float(h0));
    __half l1 = __float2half_rn(v1 - __half2float(h1));
    hi = __halves2half2(h0, h1);
    lo = __halves2half2(l0, l1);
}
__device__ __forceinline__ unsigned h2bits(float a, float b) {
    __half2 t = __floats2half2_rn(a, b);
    return *reinterpret_cast<unsigned*>(&t);
}

// ---------------------------------------------------------------------------
// Fused QK-proj + V-proj launch. Flattened grid of 4096 blocks:
//   [0,2048)   : QK proj, 3-term pair out (x=bid&7, y=(bid>>3)&127, z=bid>>10)
//   [2048,4096): V proj, 1-term + row remap (x=idx&127, y=(idx>>7)&7, z=idx>>10)
// Both tasks: 128 threads, 64x64 warp tiles, lda=ldb=512, Kper=512.
// ---------------------------------------------------------------------------
__global__ __launch_bounds__(128, 3)
void hgemm23(const __half* __restrict__ Xh_, const __half* __restrict__ Xl_,
             const __half* __restrict__ Wqkh_, const __half* __restrict__ Wqkl_,
             const __half* __restrict__ Wvh_,
             __half* __restrict__ QKh_, __half* __restrict__ QKl_,
             __half* __restrict__ Vth_) {
    extern __shared__ __align__(16) char smem[];
    const unsigned smA = smem_u32(smem);
    const unsigned smB = smA + 2 * TILEB;

    const int tid = threadIdx.x;
    const int wid = tid >> 5, lane = tid & 31;
    const int wm = wid & 1, wn = wid >> 1;

    const int bid = (int)blockIdx.x;
    const int task = bid >= 2048;
    int bx, by, zb, nterm, mode, ldc, halfoff;
    const __half *At[3], *Bt[3];
    __half *C0, *C1;
    long long coff;
    if (!task) {
        bx = bid & 7; by = (bid >> 3) & 127; zb = bid >> 10;
        long long aoff = (long long)zb * XSTR + (long long)(by * 128) * 512;
        long long boff = (long long)zb * WSTR + (long long)(bx * 128) * 512;
        At[0] = Xh_ + aoff; At[1] = Xl_ + aoff; At[2] = Xh_ + aoff;
        Bt[0] = Wqkh_ + boff; Bt[1] = Wqkh_ + boff; Bt[2] = Wqkl_ + boff;
        ldc = 1024; nterm = 3; mode = 4; halfoff = 0;
        C0 = QKh_; C1 = QKl_; coff = (long long)zb * QKSTR;
    } else {
        int idx = bid - 2048;
        bx = idx & 127; by = (idx >> 7) & 7; zb = idx >> 10;
        long long aoff = (long long)zb * WSTR + (long long)(by * 128) * 512;
        long long boff = (long long)zb * XSTR + (long long)(bx * 128) * 512;
        At[0] = At[1] = At[2] = Wvh_ + aoff;
        Bt[0] = Bt[1] = Bt[2] = Xh_ + boff;
        ldc = ROWS; nterm = 1; mode = 7; halfoff = 64 * zb;
        C0 = Vth_; C1 = nullptr; coff = 0;
    }

    const int r0 = tid >> 3, s0 = tid & 7;
    const unsigned sbase0 = (unsigned)(r0 * PADK + s0 * 8) * 2;
    const int t0 = r0 * 512 + s0 * 8;

    const int TT = nterm * 8;

#define LOAD_TILE(g, bf)                                                      \
    do {                                                                      \
        int t_ = ((g) >= 8) + ((g) >= 16);                                    \
        int kk_ = (g) - t_ * 8;                                               \
        const __half* ap = At[t_] + kk_ * 64;                                 \
        const __half* bp = Bt[t_] + kk_ * 64;                                 \
        unsigned sa = smA + (bf) * TILEB;                                     \
        unsigned sbm = smB + (bf) * TILEB;                                    \
        _Pragma("unroll")                                                     \
        for (int i_ = 0; i_ < 8; i_++) {                                      \
            cpasync16(sa + sbase0 + (unsigned)(i_ * 16 * PADK) * 2,           \
                      ap + t0 + i_ * 16 * 512);                               \
            cpasync16(sbm + sbase0 + (unsigned)(i_ * 16 * PADK) * 2,          \
                      bp + t0 + i_ * 16 * 512);                               \
        }                                                                     \
        cp_commit();                                                          \
    } while (0)

    LOAD_TILE(0, 0);

    float acc[4][8][4];
#pragma unroll
    for (int i = 0; i < 4; i++)
#pragma unroll
        for (int j = 0; j < 8; j++)
#pragma unroll
            for (int k = 0; k < 4; k++) acc[i][j][k] = 0.f;

    const int sub = lane >> 3, r8 = lane & 7;

    for (int g = 0; g < TT; g++) {
        const int bf = g & 1;
        cp_wait0();
        __syncthreads();
        if (g + 1 < TT) LOAD_TILE(g + 1, bf ^ 1);

        const unsigned ab = smA + bf * TILEB;
        const unsigned bb = smB + bf * TILEB;
#pragma unroll
        for (int ks = 0; ks < 4; ks++) {
            const int k0 = ks * 16;
            unsigned a[4][4];
#pragma unroll
            for (int mi = 0; mi < 4; mi++) {
                int mrow = wm * 64 + mi * 16 + r8 + (sub & 1) * 8;
                int mcol = k0 + (sub >> 1) * 8;
                ldm4(a[mi][0], a[mi][1], a[mi][2], a[mi][3],
                     ab + (unsigned)(mrow * PADK + mcol) * 2);
            }
#pragma unroll
            for (int nh = 0; nh < 2; nh++) {
                unsigned b[4][2];
#pragma unroll
                for (int np = 0; np < 2; np++) {
                    int nrow = wn * 64 + nh * 32 + np * 16 + r8 + (sub >> 1) * 8;
                    int kcol = k0 + (sub & 1) * 8;
                    unsigned q0, q1, q2, q3;
                    ldm4(q0, q1, q2, q3, bb + (unsigned)(nrow * PADK + kcol) * 2);
                    b[np * 2][0] = q0; b[np * 2][1] = q1;
                    b[np * 2 + 1][0] = q2; b[np * 2 + 1][1] = q3;
                }
#pragma unroll
                for (int mi = 0; mi < 4; mi++)
#pragma unroll
                    for (int ni = 0; ni < 4; ni++)
                        mma16816(acc[mi][nh * 4 + ni], a[mi], b[ni]);
            }
        }
        __syncthreads();
    }
#undef LOAD_TILE

    const int trow = lane >> 2, tcol = (lane & 3) * 2;

#pragma unroll
    for (int mi = 0; mi < 4; mi++) {
#pragma unroll
        for (int ni = 0; ni < 8; ni++) {
            int rg = by * 128 + wm * 64 + mi * 16 + trow;
            int cg = bx * 128 + wn * 64 + ni * 8 + tcol;
            float* ac = acc[mi][ni];
            if (mode == 4) {
                __half2 h, l;
                size_t o0 = coff + (size_t)rg * ldc + cg;
                size_t o1 = coff + (size_t)(rg + 8) * ldc + cg;
                split2(ac[0], ac[1], h, l);
                *(__half2*)(C0 + o0) = h;
                *(__half2*)(C1 + o0) = l;
                split2(ac[2], ac[3], h, l);
                *(__half2*)(C0 + o1) = h;
                *(__half2*)(C1 + o1) = l;
            } else {  // mode 7: single fp16 out + V row remap
                int ra = ((rg >> 6) << 7) + (rg & 63) + halfoff;
                int rb0 = rg + 8;
                int rb = ((rb0 >> 6) << 7) + (rb0 & 63) + halfoff;
                *(__half2*)(C0 + (size_t)ra * ldc + cg) =
                    __floats2half2_rn(ac[0], ac[1]);
                *(__half2*)(C0 + (size_t)rb * ldc + cg) =
                    __floats2half2_rn(ac[2], ac[3]);
            }
        }
    }
}

// ---------------------------------------------------------------------------
// Generic HMMA GEMM (R13-proven, used for out-proj): 128 thr, 64x64 tiles.
// ---------------------------------------------------------------------------
__global__ __launch_bounds__(128, 3)
void hgemm(const __half* __restrict__ A0, long long sAb, int lda,
           const __half* __restrict__ B0, long long sBb, int ldb,
           float* __restrict__ C0, long long sCb, int ldc, int Kper) {
    extern __shared__ __align__(16) char smem[];
    const unsigned smA = smem_u32(smem);
    const unsigned smB = smA + 2 * TILEB;

    const int tid = threadIdx.x;
    const int wid = tid >> 5, lane = tid & 31;
    const int wm = wid & 1, wn = wid >> 1;

    const int zb = (int)blockIdx.z;
    const __half* Ab = A0 + (long long)zb * sAb + (long long)(blockIdx.y * 128) * lda;
    const __half* Bb = B0 + (long long)zb * sBb + (long long)(blockIdx.x * 128) * ldb;

    const int r0 = tid >> 3, s0 = tid & 7;
    const unsigned sbase0 = (unsigned)(r0 * PADK + s0 * 8) * 2;
    const int ta0 = r0 * lda + s0 * 8, tb0 = r0 * ldb + s0 * 8;

    const int TT = Kper >> 6;

#define LOAD_TILE(g, bf)                                                      \
    do {                                                                      \
        const __half* ap = Ab + (g) * 64;                                     \
        const __half* bp = Bb + (g) * 64;                                     \
        unsigned sa = smA + (bf) * TILEB;                                     \
        unsigned sbm = smB + (bf) * TILEB;                                    \
        _Pragma("unroll")                                                     \
        for (int i_ = 0; i_ < 8; i_++) {                                      \
            cpasync16(sa + sbase0 + (unsigned)(i_ * 16 * PADK) * 2,           \
                      ap + ta0 + i_ * 16 * lda);                              \
            cpasync16(sbm + sbase0 + (unsigned)(i_ * 16 * PADK) * 2,          \
                      bp + tb0 + i_ * 16 * ldb);                              \
        }                                                                     \
        cp_commit();                                                          \
    } while (0)

    LOAD_TILE(0, 0);

    float acc[4][8][4];
#pragma unroll
    for (int i = 0; i < 4; i++)
#pragma unroll
        for (int j = 0; j < 8; j++)
#pragma unroll
            for (int k = 0; k < 4; k++) acc[i][j][k] = 0.f;

    const int sub = lane >> 3, r8 = lane & 7;

    for (int g = 0; g < TT; g++) {
        const int bf = g & 1;
        cp_wait0();
        __syncthreads();
        if (g + 1 < TT) LOAD_TILE(g + 1, bf ^ 1);

        const unsigned ab = smA + bf * TILEB;
        const unsigned bb = smB + bf * TILEB;
#pragma unroll
        for (int ks = 0; ks < 4; ks++) {
            const int k0 = ks * 16;
            unsigned a[4][4];
#pragma unroll
            for (int mi = 0; mi < 4; mi++) {
                int mrow = wm * 64 + mi * 16 + r8 + (sub & 1) * 8;
                int mcol = k0 + (sub >> 1) * 8;
                ldm4(a[mi][0], a[mi][1], a[mi][2], a[mi][3],
                     ab + (unsigned)(mrow * PADK + mcol) * 2);
            }
#pragma unroll
            for (int nh = 0; nh < 2; nh++) {
                unsigned b[4][2];
#pragma unroll
                for (int np = 0; np < 2; np++) {
                    int nrow = wn * 64 + nh * 32 + np * 16 + r8 + (sub >> 1) * 8;
                    int kcol = k0 + (sub & 1) * 8;
                    unsigned q0, q1, q2, q3;
                    ldm4(q0, q1, q2, q3, bb + (unsigned)(nrow * PADK + kcol) * 2);
                    b[np * 2][0] = q0; b[np * 2][1] = q1;
                    b[np * 2 + 1][0] = q2; b[np * 2 + 1][1] = q3;
                }
#pragma unroll
                for (int mi = 0; mi < 4; mi++)
#pragma unroll
                    for (int ni = 0; ni < 4; ni++)
                        mma16816(acc[mi][nh * 4 + ni], a[mi], b[ni]);
            }
        }
        __syncthreads();
    }
#undef LOAD_TILE

    const int trow = lane >> 2, tcol = (lane & 3) * 2;
    const long long coff = (long long)zb * sCb;

#pragma unroll
    for (int mi = 0; mi < 4; mi++) {
#pragma unroll
        for (int ni = 0; ni < 8; ni++) {
            int rg = blockIdx.y * 128 + wm * 64 + mi * 16 + trow;
            int cg = blockIdx.x * 128 + wn * 64 + ni * 8 + tcol;
            float* ac = acc[mi][ni];
            float* p0 = C0 + coff + (size_t)rg * ldc + cg;
            float* p1 = C0 + coff + (size_t)(rg + 8) * ldc + cg;
            *(float2*)p0 = make_float2(ac[0], ac[1]);
            *(float2*)p1 = make_float2(ac[2], ac[3]);
        }
    }
}

// ---------------------------------------------------------------------------
// Flash attention, FA2-style register softmax (R12-proven, unchanged).
// ---------------------------------------------------------------------------
__global__ __launch_bounds__(256, 1)
void flash_attn(const __half* __restrict__ QKhB, const __half* __restrict__ QKlB,
                const __half* __restrict__ VhB,
                __half* __restrict__ H0B, __half* __restrict__ H1B) {
    extern __shared__ __align__(16) char smem[];
    const unsigned sb = smem_u32(smem);

    const int tid = threadIdx.x, wid = tid >> 5, lane = tid & 31;
    const int sub = lane >> 3, r8 = lane & 7;
    const int trow = lane >> 2, tq2 = (lane & 3) * 2;
    const int qt = blockIdx.x, z = blockIdx.y;
    const int h = z >> 4, b = z & 15;
    const int s = blockIdx.z;

    const __half* QKh = QKhB + (size_t)s * QKSTR;
    const __half* QKl = QKlB + (size_t)s * QKSTR;
    const __half* Vh  = VhB  + (size_t)s * 16777216;
    __half* C0 = H0B + s * 64;
    __half* C1 = H1B + s * 64;

    {
        const size_t rbase = (size_t)(b << 10) + qt * 128;
#pragma unroll
        for (int i = 0; i < 4; i++) {
            int c = tid + i * 256;
            int r = c >> 3, sc = c & 7;
            unsigned sof = (unsigned)(r * PADK + sc * 8) * 2;
            size_t go = (rbase + r) * 1024 + h * 64 + sc * 8;
            cpasync16(sb + OFF_Q + sof, QKh + go);
            cpasync16(sb + OFF_Q + 18432 + sof, QKl + go);
        }
    }

#define LOAD_KV(kt, bi)                                                       \
    do {                                                                      \
        unsigned kb = sb + OFF_KV + (bi) * KVBUF;                             \
        _Pragma("unroll")                                                     \
        for (int i_ = 0; i_ < 2; i_++) {                                      \
            int c_ = tid + i_ * 256;                                          \
            int r_ = c_ >> 3, sc_ = c_ & 7;                                   \
            cpasync16(kb + (unsigned)(r_ * PADK + sc_ * 8) * 2,               \
                      QKh + ((size_t)(b << 10) + (kt) * 64 + r_) * 1024 +     \
                          512 + h * 64 + sc_ * 8);                            \
        }                                                                     \
        _Pragma("unroll")                                                     \
        for (int i_ = 0; i_ < 4; i_++) {                                      \
            int c_ = tid + i_ * 256;                                          \
            int r_ = c_ >> 3, sc_ = c_ & 7;                                   \
            cpasync16(kb + 9216 + (unsigned)(r_ * PADK + sc_ * 8) * 2,        \
                      Vh + (size_t)(h * 128 + r_) * 16384 +                   \
                          (size_t)(b << 10) + (kt) * 64 + sc_ * 8);           \
        }                                                                     \
        cp_commit();                                                          \
    } while (0)

    LOAD_KV(0, 0);
    cp_wait0();

    float O[16][4];
#pragma unroll
    for (int i = 0; i < 16; i++)
#pragma unroll
        for (int j = 0; j < 4; j++) O[i][j] = 0.f;
    float m0 = -1e30f, m1 = -1e30f, l0 = 0.f, l1 = 0.f;

    for (int kt = 0; kt < NKT; kt++) {
        const int bi = kt & 1;
        if (kt) cp_wait0();
        __syncthreads();
        if (kt + 1 < NKT) LOAD_KV(kt + 1, bi ^ 1);

        const unsigned Kb = sb + OFF_KV + bi * KVBUF;
        const unsigned Vb = Kb + 9216;

        float sc[8][4];
#pragma unroll
        for (int t = 0; t < 8; t++)
#pragma unroll
            for (int j = 0; j < 4; j++) sc[t][j] = 0.f;

#pragma unroll
        for (int ks = 0; ks < 4; ks++) {
            const int k0 = ks * 16;
            unsigned ah[4], al[4];
            unsigned offa = (unsigned)((wid * 16 + r8 + (sub & 1) * 8) * PADK +
                                       k0 + (sub >> 1) * 8) * 2;
            ldm4(ah[0], ah[1], ah[2], ah[3], sb + OFF_Q + offa);
            ldm4(al[0], al[1], al[2], al[3], sb + OFF_Q + 18432 + offa);
            unsigned bk[8][2];
#pragma unroll
            for (int nb = 0; nb < 4; nb++) {
                unsigned offb = (unsigned)((nb * 16 + r8 + (sub >> 1) * 8) * PADK +
                                           k0 + (sub & 1) * 8) * 2;
                unsigned q0, q1, q2, q3;
                ldm4(q0, q1, q2, q3, Kb + offb);
                bk[2 * nb][0] = q0; bk[2 * nb][1] = q1;
                bk[2 * nb + 1][0] = q2; bk[2 * nb + 1][1] = q3;
            }
#pragma unroll
            for (int t = 0; t < 8; t++) {
                mma16816(sc[t], ah, bk[t]);
                mma16816(sc[t], al, bk[t]);
            }
        }

        float mt0 = sc[0][0], mt1 = sc[0][2];
#pragma unroll
        for (int t = 0; t < 8; t++) {
            mt0 = fmaxf(mt0, fmaxf(sc[t][0], sc[t][1]));
            mt1 = fmaxf(mt1, fmaxf(sc[t][2], sc[t][3]));
        }
        mt0 = fmaxf(mt0, __shfl_xor_sync(~0u, mt0, 1));
        mt0 = fmaxf(mt0, __shfl_xor_sync(~0u, mt0, 2));
        mt1 = fmaxf(mt1, __shfl_xor_sync(~0u, mt1, 1));
        mt1 = fmaxf(mt1, __shfl_xor_sync(~0u, mt1, 2));
        float mn0 = fmaxf(m0, mt0), mn1 = fmaxf(m1, mt1);
        float f0 = __expf(m0 - mn0), f1 = __expf(m1 - mn1);
        float sum0 = 0.f, sum1 = 0.f;
        unsigned pf[4][4];
#pragma unroll
        for (int kk = 0; kk < 4; kk++) {
            float e00 = __expf(sc[2 * kk][0] - mn0);
            float e01 = __expf(sc[2 * kk][1] - mn0);
            float e02 = __expf(sc[2 * kk][2] - mn1);
            float e03 = __expf(sc[2 * kk][3] - mn1);
            float e10 = __expf(sc[2 * kk + 1][0] - mn0);
            float e11 = __expf(sc[2 * kk + 1][1] - mn0);
            float e12 = __expf(sc[2 * kk + 1][2] - mn1);
            float e13 = __expf(sc[2 * kk + 1][3] - mn1);
            sum0 += e00 + e01 + e10 + e11;
            sum1 += e02 + e03 + e12 + e13;
            pf[kk][0] = h2bits(e00, e01);
            pf[kk][1] = h2bits(e02, e03);
            pf[kk][2] = h2bits(e10, e11);
            pf[kk][3] = h2bits(e12, e13);
        }
        sum0 += __shfl_xor_sync(~0u, sum0, 1);
        sum0 += __shfl_xor_sync(~0u, sum0, 2);
        sum1 += __shfl_xor_sync(~0u, sum1, 1);
        sum1 += __shfl_xor_sync(~0u, sum1, 2);
        l0 = l0 * f0 + sum0;  m0 = mn0;
        l1 = l1 * f1 + sum1;  m1 = mn1;

#pragma unroll
        for (int ni = 0; ni < 16; ni++) {
            O[ni][0] *= f0; O[ni][1] *= f0;
            O[ni][2] *= f1; O[ni][3] *= f1;
        }
#pragma unroll
        for (int kk = 0; kk < 4; kk++) {
            const int k0 = kk * 16;
            unsigned bv[16][2];
#pragma unroll
            for (int nb = 0; nb < 8; nb++) {
                unsigned offv = (unsigned)((nb * 16 + r8 + (sub >> 1) * 8) * PADK +
                                           k0 + (sub & 1) * 8) * 2;
                unsigned q0, q1, q2, q3;
                ldm4(q0, q1, q2, q3, Vb + offv);
                bv[2 * nb][0] = q0; bv[2 * nb][1] = q1;
                bv[2 * nb + 1][0] = q2; bv[2 * nb + 1][1] = q3;
            }
#pragma unroll
            for (int ni = 0; ni < 16; ni++)
                mma16816(O[ni], pf[kk], bv[ni]);
        }
    }
#undef LOAD_KV

    const float inv0 = 1.f / l0, inv1 = 1.f / l1;
    const long long coff = 128LL * h + 1048576LL * b;
    const int rg0 = qt * 128 + wid * 16 + trow, rg1 = rg0 + 8;
#pragma unroll
    for (int ni = 0; ni < 16; ni++) {
        int cg = ni * 8 + tq2;
        __half* base = (cg < 64) ? C0 : C1;
        int cl = cg & 63;
        *(__half2*)(base + coff + (size_t)rg0 * 1024 + cl) =
            __floats2half2_rn(O[ni][0] * inv0, O[ni][1] * inv0);
        *(__half2*)(base + coff + (size_t)rg1 * 1024 + cl) =
            __floats2half2_rn(O[ni][2] * inv1, O[ni][3] * inv1);
    }
}

// ---------------------------------------------------------------------------
// Fused prep: 28672 blocks. [0,12288): weight repack (task = bid/2048).
// [12288,28672): X conversion (8192 blocks per stream).
// ---------------------------------------------------------------------------
__global__ void prep_all(const float* __restrict__ Wqn, const float* __restrict__ Wkn,
                         const float* __restrict__ Wqp, const float* __restrict__ Wkp,
                         const float* __restrict__ Wvn, const float* __restrict__ Wvp,
                         const float* __restrict__ Won, const float* __restrict__ Wop,
                         const float* __restrict__ Xn, const float* __restrict__ Xp,
                         __half* __restrict__ Wqkh, __half* __restrict__ Wqkl,
                         __half* __restrict__ Wvh, __half* __restrict__ Woh,
                         __half* __restrict__ Yh, __half* __restrict__ Yl) {
    int bid = blockIdx.x;
    if (bid < 12288) {
        int task = bid >> 11;
        int idx = (bid & 2047) * 256 + threadIdx.x;
        if (idx >= 524288) return;
        int st = task & 1;
        if (task < 2) {
            const float* Wq = st ? Wqp : Wqn;
            const float* Wk = st ? Wkp : Wkn;
            int j = idx >> 9, d = idx & 511;
            int jj = j & 511;
            float v;
            if (j < 512)
                v = Wq[((size_t)((jj >> 6) * 512 + d)) * 64 + (jj & 63)] * 0.125f;
            else
                v = Wk[((size_t)((jj >> 6) * 512 + d)) * 64 + (jj & 63)];
            __half h = __float2half_rn(v);
            Wqkh[(size_t)st * WSTR + idx] = h;
            Wqkl[(size_t)st * WSTR + idx] = __float2half_rn(v - __half2float(h));
        } else if (task < 4) {
            const float* Wv = st ? Wvp : Wvn;
            int j = idx >> 9, d = idx & 511;
            Wvh[(size_t)st * WSTR + idx] =
                __float2half_rn(Wv[((size_t)((j >> 6) * 512 + d)) * 64 + (j & 63)]);
        } else {
            const float* Wo = st ? Wop : Won;
            int e = idx >> 10, j = idx & 1023;
            Woh[(size_t)st * WSTR + idx] = __float2half_rn(Wo[(size_t)j * 512 + e]);
        }
    } else {
        int r = bid - 12288;
        int st = r >> 13;
        int i = (r & 8191) * 256 + threadIdx.x;
        if (i >= ROWS * 512 / 4) return;
        const float* X = st ? Xp : Xn;
        float4 v = ((const float4*)X)[i];
        __half2 h0, l0a, h1, l1a;
        split2(v.x, v.y, h0, l0a);
        split2(v.z, v.w, h1, l1a);
        uint2 uh, ul;
        uh.x = *reinterpret_cast<unsigned*>(&h0);
        uh.y = *reinterpret_cast<unsigned*>(&h1);
        ul.x = *reinterpret_cast<unsigned*>(&l0a);
        ul.y = *reinterpret_cast<unsigned*>(&l1a);
        ((uint2*)(Yh + (size_t)st * XSTR))[i] = uh;
        ((uint2*)(Yl + (size_t)st * XSTR))[i] = ul;
    }
}

// ---------------------------------------------------------------------------
// Host launcher: 4 kernel launches
// ---------------------------------------------------------------------------
extern "C" void kernel_launch(void* const* d_in, const int* in_sizes, int n_in,
                              void* d_out, int out_size) {
    const float* Xn  = (const float*)d_in[0];
    const float* Xp  = (const float*)d_in[1];
    const float* Wqn = (const float*)d_in[2];
    const float* Wqp = (const float*)d_in[3];
    const float* Wkn = (const float*)d_in[4];
    const float* Wkp = (const float*)d_in[5];
    const float* Wvn = (const float*)d_in[6];
    const float* Wvp = (const float*)d_in[7];
    const float* Won = (const float*)d_in[8];
    const float* Wop = (const float*)d_in[9];
    float* out = (float*)d_out;

    __half *Wqkh, *Wqkl, *Wvh, *Woh, *Xh, *Xl, *QKh, *QKl, *Vth, *H;
    cudaGetSymbolAddress((void**)&Wqkh, g_Wqkh);
    cudaGetSymbolAddress((void**)&Wqkl, g_Wqkl);
    cudaGetSymbolAddress((void**)&Wvh,  g_Wvh);
    cudaGetSymbolAddress((void**)&Woh,  g_Woh);
    cudaGetSymbolAddress((void**)&Xh,   g_Xh);
    cudaGetSymbolAddress((void**)&Xl,   g_Xl);
    cudaGetSymbolAddress((void**)&QKh,  g_QKh);
    cudaGetSymbolAddress((void**)&QKl,  g_QKl);
    cudaGetSymbolAddress((void**)&Vth,  g_Vth);
    cudaGetSymbolAddress((void**)&H,    g_H);

    cudaFuncSetAttribute(hgemm23, cudaFuncAttributeMaxDynamicSharedMemorySize,
                         GEMM_SMEM);
    cudaFuncSetAttribute(hgemm, cudaFuncAttributeMaxDynamicSharedMemorySize,
                         GEMM_SMEM);
    cudaFuncSetAttribute(flash_attn, cudaFuncAttributeMaxDynamicSharedMemorySize,
                         FA_SMEM);

    // 1) fused prep (weights + inputs)
    prep_all<<<28672, 256>>>(Wqn, Wkn, Wqp, Wkp, Wvn, Wvp, Won, Wop, Xn, Xp,
                             Wqkh, Wqkl, Wvh, Woh, Xh, Xl);

    // 2) fused QK-proj (3-term pair) + V-proj (1-term remap), both streams
    hgemm23<<<4096, 128, GEMM_SMEM>>>(Xh, Xl, Wqkh, Wqkl, Wvh, QKh, QKl, Vth);

    // 3) flash attention (FA2 register softmax), both streams (z)
    flash_attn<<<dim3(8, 128, 2), 256, FA_SMEM>>>(
        QKh, QKl, Vth, H, H + QKSTR);

    // 4) output projections, fp32 out, both streams (z)
    hgemm<<<dim3(4, 128, 2), 128, GEMM_SMEM>>>(
        H, HSTR, 1024, Woh, WSTR, 1024, out, OSTR, 512, 1024);
}

// round 16
// speedup vs baseline: 1.0736x; 1.0390x over previous
#include <cuda_runtime.h>
#include <cuda_fp16.h>

// ===========================================================================
// B=16, N=1024, D=512, H=8, dk=64. ROWS=16384.
// HMMA (mma.sync m16n8k16), fp32 accum, split-fp16 where precision needs it:
//   QK proj: 3-term (Xh*Wh + Xl*Wh + Xh*Wl), pair out
//   S      : 2-term (Qh*Kh + Ql*Kh); flash with register-resident softmax
//   V proj : 1-term, out proj: 1-term, PV: V-hi only
// 4 launches. flash v3: q-tile 256, 32 q-rows per warp (K/V reuse 2x).
// ===========================================================================
#define ROWS 16384
#define PADK 72
#define TILEB (128 * PADK * 2)
#define GEMM_SMEM (4 * TILEB)

#define XSTR  ((long long)ROWS * 512)
#define WSTR  (524288LL)
#define QKSTR ((long long)ROWS * 1024)
#define HSTR  ((long long)ROWS * 1024)
#define OSTR  ((long long)ROWS * 512)

// Flash smem (bytes): Qh 36864 | Ql 36864 | 2 x (Kh 9216 + V 18432)
#define NKT    16
#define OFF_Q  0
#define QBYTES 36864
#define OFF_KV 73728
#define KVBUF  27648
#define FA_SMEM 129024

// ---------------------------------------------------------------------------
// Static device scratch
// ---------------------------------------------------------------------------
__device__ __half g_Wqkh[2][524288], g_Wqkl[2][524288];
__device__ __half g_Wvh [2][524288];
__device__ __half g_Woh [2][524288];
__device__ __half g_Xh  [2][8388608], g_Xl[2][8388608];
__device__ __half g_QKh [2][16777216], g_QKl[2][16777216];
__device__ __half g_Vth [2][16777216];
__device__ __half g_H   [2][16777216];

// ---------------------------------------------------------------------------
// PTX helpers
// ---------------------------------------------------------------------------
__device__ __forceinline__ unsigned smem_u32(const void* p) {
    unsigned a;
    asm("{ .reg .u64 t; cvta.to.shared.u64 t, %1; cvt.u32.u64 %0, t; }"
        : "=r"(a) : "l"(p));
    return a;
}
__device__ __forceinline__ void cpasync16(unsigned s, const void* g) {
    asm volatile("cp.async.cg.shared.global [%0], [%1], 16;" :: "r"(s), "l"(g));
}
__device__ __forceinline__ void cp_commit() {
    asm volatile("cp.async.commit_group;" ::: "memory");
}
__device__ __forceinline__ void cp_wait0() {
    asm volatile("cp.async.wait_group 0;" ::: "memory");
}
__device__ __forceinline__ void ldm4(unsigned& r0, unsigned& r1, unsigned& r2,
                                     unsigned& r3, unsigned a) {
    asm volatile("ldmatrix.sync.aligned.m8n8.x4.shared.b16 {%0,%1,%2,%3}, [%4];"
                 : "=r"(r0), "=r"(r1), "=r"(r2), "=r"(r3) : "r"(a));
}
__device__ __forceinline__ void mma16816(float* c, const unsigned* a,
                                         const unsigned* b) {
    asm volatile(
        "mma.sync.aligned.m16n8k16.row.col.f32.f16.f16.f32 "
        "{%0,%1,%2,%3}, {%4,%5,%6,%7}, {%8,%9}, {%0,%1,%2,%3};"
        : "+f"(c[0]), "+f"(c[1]), "+f"(c[2]), "+f"(c[3])
        : "r"(a[0]), "r"(a[1]), "r"(a[2]), "r"(a[3]), "r"(b[0]), "r"(b[1]));
}
__device__ __forceinline__ void split2(float v0, float v1, __half2& hi, __half2& lo) {
    __half h0 = __float2half_rn(v0), h1 = __float2half_rn(v1);
    __half l0 = __float2half_rn(v0 - __half2float(h0));
    __half l1 = __float2half_rn(v1 - __half2float(h1));
    hi = __halves2half2(h0, h1);
    lo = __halves2half2(l0, l1);
}
__device__ __forceinline__ unsigned h2bits(float a, float b) {
    __half2 t = __floats2half2_rn(a, b);
    return *reinterpret_cast<unsigned*>(&t);
}

// ---------------------------------------------------------------------------
// Fused QK-proj + V-proj launch (R15-proven). Flattened grid of 4096 blocks.
// ---------------------------------------------------------------------------
__global__ __launch_bounds__(128, 3)
void hgemm23(const __half* __restrict__ Xh_, const __half* __restrict__ Xl_,
             const __half* __restrict__ Wqkh_, const __half* __restrict__ Wqkl_,
             const __half* __restrict__ Wvh_,
             __half* __restrict__ QKh_, __half* __restrict__ QKl_,
             __half* __restrict__ Vth_) {
    extern __shared__ __align__(16) char smem[];
    const unsigned smA = smem_u32(smem);
    const unsigned smB = smA + 2 * TILEB;

    const int tid = threadIdx.x;
    const int wid = tid >> 5, lane = tid & 31;
    const int wm = wid & 1, wn = wid >> 1;

    const int bid = (int)blockIdx.x;
    const int task = bid >= 2048;
    int bx, by, zb, nterm, mode, ldc, halfoff;
    const __half *At[3], *Bt[3];
    __half *C0, *C1;
    long long coff;
    if (!task) {
        bx = bid & 7; by = (bid >> 3) & 127; zb = bid >> 10;
        long long aoff = (long long)zb * XSTR + (long long)(by * 128) * 512;
        long long boff = (long long)zb * WSTR + (long long)(bx * 128) * 512;
        At[0] = Xh_ + aoff; At[1] = Xl_ + aoff; At[2] = Xh_ + aoff;
        Bt[0] = Wqkh_ + boff; Bt[1] = Wqkh_ + boff; Bt[2] = Wqkl_ + boff;
        ldc = 1024; nterm = 3; mode = 4; halfoff = 0;
        C0 = QKh_; C1 = QKl_; coff = (long long)zb * QKSTR;
    } else {
        int idx = bid - 2048;
        bx = idx & 127; by = (idx >> 7) & 7; zb = idx >> 10;
        long long aoff = (long long)zb * WSTR + (long long)(by * 128) * 512;
        long long boff = (long long)zb * XSTR + (long long)(bx * 128) * 512;
        At[0] = At[1] = At[2] = Wvh_ + aoff;
        Bt[0] = Bt[1] = Bt[2] = Xh_ + boff;
        ldc = ROWS; nterm = 1; mode = 7; halfoff = 64 * zb;
        C0 = Vth_; C1 = nullptr; coff = 0;
    }

    const int r0 = tid >> 3, s0 = tid & 7;
    const unsigned sbase0 = (unsigned)(r0 * PADK + s0 * 8) * 2;
    const int t0 = r0 * 512 + s0 * 8;

    const int TT = nterm * 8;

#define LOAD_TILE(g, bf)                                                      \
    do {                                                                      \
        int t_ = ((g) >= 8) + ((g) >= 16);                                    \
        int kk_ = (g) - t_ * 8;                                               \
        const __half* ap = At[t_] + kk_ * 64;                                 \
        const __half* bp = Bt[t_] + kk_ * 64;                                 \
        unsigned sa = smA + (bf) * TILEB;                                     \
        unsigned sbm = smB + (bf) * TILEB;                                    \
        _Pragma("unroll")                                                     \
        for (int i_ = 0; i_ < 8; i_++) {                                      \
            cpasync16(sa + sbase0 + (unsigned)(i_ * 16 * PADK) * 2,           \
                      ap + t0 + i_ * 16 * 512);                               \
            cpasync16(sbm + sbase0 + (unsigned)(i_ * 16 * PADK) * 2,          \
                      bp + t0 + i_ * 16 * 512);                               \
        }                                                                     \
        cp_commit();                                                          \
    } while (0)

    LOAD_TILE(0, 0);

    float acc[4][8][4];
#pragma unroll
    for (int i = 0; i < 4; i++)
#pragma unroll
        for (int j = 0; j < 8; j++)
#pragma unroll
            for (int k = 0; k < 4; k++) acc[i][j][k] = 0.f;

    const int sub = lane >> 3, r8 = lane & 7;

    for (int g = 0; g < TT; g++) {
        const int bf = g & 1;
        cp_wait0();
        __syncthreads();
        if (g + 1 < TT) LOAD_TILE(g + 1, bf ^ 1);

        const unsigned ab = smA + bf * TILEB;
        const unsigned bb = smB + bf * TILEB;
#pragma unroll
        for (int ks = 0; ks < 4; ks++) {
            const int k0 = ks * 16;
            unsigned a[4][4];
#pragma unroll
            for (int mi = 0; mi < 4; mi++) {
                int mrow = wm * 64 + mi * 16 + r8 + (sub & 1) * 8;
                int mcol = k0 + (sub >> 1) * 8;
                ldm4(a[mi][0], a[mi][1], a[mi][2], a[mi][3],
                     ab + (unsigned)(mrow * PADK + mcol) * 2);
            }
#pragma unroll
            for (int nh = 0; nh < 2; nh++) {
                unsigned b[4][2];
#pragma unroll
                for (int np = 0; np < 2; np++) {
                    int nrow = wn * 64 + nh * 32 + np * 16 + r8 + (sub >> 1) * 8;
                    int kcol = k0 + (sub & 1) * 8;
                    unsigned q0, q1, q2, q3;
                    ldm4(q0, q1, q2, q3, bb + (unsigned)(nrow * PADK + kcol) * 2);
                    b[np * 2][0] = q0; b[np * 2][1] = q1;
                    b[np * 2 + 1][0] = q2; b[np * 2 + 1][1] = q3;
                }
#pragma unroll
                for (int mi = 0; mi < 4; mi++)
#pragma unroll
                    for (int ni = 0; ni < 4; ni++)
                        mma16816(acc[mi][nh * 4 + ni], a[mi], b[ni]);
            }
        }
        __syncthreads();
    }
#undef LOAD_TILE

    const int trow = lane >> 2, tcol = (lane & 3) * 2;

#pragma unroll
    for (int mi = 0; mi < 4; mi++) {
#pragma unroll
        for (int ni = 0; ni < 8; ni++) {
            int rg = by * 128 + wm * 64 + mi * 16 + trow;
            int cg = bx * 128 + wn * 64 + ni * 8 + tcol;
            float* ac = acc[mi][ni];
            if (mode == 4) {
                __half2 h, l;
                size_t o0 = coff + (size_t)rg * ldc + cg;
                size_t o1 = coff + (size_t)(rg + 8) * ldc + cg;
                split2(ac[0], ac[1], h, l);
                *(__half2*)(C0 + o0) = h;
                *(__half2*)(C1 + o0) = l;
                split2(ac[2], ac[3], h, l);
                *(__half2*)(C0 + o1) = h;
                *(__half2*)(C1 + o1) = l;
            } else {
                int ra = ((rg >> 6) << 7) + (rg & 63) + halfoff;
                int rb0 = rg + 8;
                int rb = ((rb0 >> 6) << 7) + (rb0 & 63) + halfoff;
                *(__half2*)(C0 + (size_t)ra * ldc + cg) =
                    __floats2half2_rn(ac[0], ac[1]);
                *(__half2*)(C0 + (size_t)rb * ldc + cg) =
                    __floats2half2_rn(ac[2], ac[3]);
            }
        }
    }
}

// ---------------------------------------------------------------------------
// Generic HMMA GEMM (out-proj): 128 thr, 64x64 tiles (R13-proven).
// ---------------------------------------------------------------------------
__global__ __launch_bounds__(128, 3)
void hgemm(const __half* __restrict__ A0, long long sAb, int lda,
           const __half* __restrict__ B0, long long sBb, int ldb,
           float* __restrict__ C0, long long sCb, int ldc, int Kper) {
    extern __shared__ __align__(16) char smem[];
    const unsigned smA = smem_u32(smem);
    const unsigned smB = smA + 2 * TILEB;

    const int tid = threadIdx.x;
    const int wid = tid >> 5, lane = tid & 31;
    const int wm = wid & 1, wn = wid >> 1;

    const int zb = (int)blockIdx.z;
    const __half* Ab = A0 + (long long)zb * sAb + (long long)(blockIdx.y * 128) * lda;
    const __half* Bb = B0 + (long long)zb * sBb + (long long)(blockIdx.x * 128) * ldb;

    const int r0 = tid >> 3, s0 = tid & 7;
    const unsigned sbase0 = (unsigned)(r0 * PADK + s0 * 8) * 2;
    const int ta0 = r0 * lda + s0 * 8, tb0 = r0 * ldb + s0 * 8;

    const int TT = Kper >> 6;

#define LOAD_TILE(g, bf)                                                      \
    do {                                                                      \
        const __half* ap = Ab + (g) * 64;                                     \
        const __half* bp = Bb + (g) * 64;                                     \
        unsigned sa = smA + (bf) * TILEB;                                     \
        unsigned sbm = smB + (bf) * TILEB;                                    \
        _Pragma("unroll")                                                     \
        for (int i_ = 0; i_ < 8; i_++) {                                      \
            cpasync16(sa + sbase0 + (unsigned)(i_ * 16 * PADK) * 2,           \
                      ap + ta0 + i_ * 16 * lda);                              \
            cpasync16(sbm + sbase0 + (unsigned)(i_ * 16 * PADK) * 2,          \
                      bp + tb0 + i_ * 16 * ldb);                              \
        }                                                                     \
        cp_commit();                                                          \
    } while (0)

    LOAD_TILE(0, 0);

    float acc[4][8][4];
#pragma unroll
    for (int i = 0; i < 4; i++)
#pragma unroll
        for (int j = 0; j < 8; j++)
#pragma unroll
            for (int k = 0; k < 4; k++) acc[i][j][k] = 0.f;

    const int sub = lane >> 3, r8 = lane & 7;

    for (int g = 0; g < TT; g++) {
        const int bf = g & 1;
        cp_wait0();
        __syncthreads();
        if (g + 1 < TT) LOAD_TILE(g + 1, bf ^ 1);

        const unsigned ab = smA + bf * TILEB;
        const unsigned bb = smB + bf * TILEB;
#pragma unroll
        for (int ks = 0; ks < 4; ks++) {
            const int k0 = ks * 16;
            unsigned a[4][4];
#pragma unroll
            for (int mi = 0; mi < 4; mi++) {
                int mrow = wm * 64 + mi * 16 + r8 + (sub & 1) * 8;
                int mcol = k0 + (sub >> 1) * 8;
                ldm4(a[mi][0], a[mi][1], a[mi][2], a[mi][3],
                     ab + (unsigned)(mrow * PADK + mcol) * 2);
            }
#pragma unroll
            for (int nh = 0; nh < 2; nh++) {
                unsigned b[4][2];
#pragma unroll
                for (int np = 0; np < 2; np++) {
                    int nrow = wn * 64 + nh * 32 + np * 16 + r8 + (sub >> 1) * 8;
                    int kcol = k0 + (sub & 1) * 8;
                    unsigned q0, q1, q2, q3;
                    ldm4(q0, q1, q2, q3, bb + (unsigned)(nrow * PADK + kcol) * 2);
                    b[np * 2][0] = q0; b[np * 2][1] = q1;
                    b[np * 2 + 1][0] = q2; b[np * 2 + 1][1] = q3;
                }
#pragma unroll
                for (int mi = 0; mi < 4; mi++)
#pragma unroll
                    for (int ni = 0; ni < 4; ni++)
                        mma16816(acc[mi][nh * 4 + ni], a[mi], b[ni]);
            }
        }
        __syncthreads();
    }
#undef LOAD_TILE

    const int trow = lane >> 2, tcol = (lane & 3) * 2;
    const long long coff = (long long)zb * sCb;

#pragma unroll
    for (int mi = 0; mi < 4; mi++) {
#pragma unroll
        for (int ni = 0; ni < 8; ni++) {
            int rg = blockIdx.y * 128 + wm * 64 + mi * 16 + trow;
            int cg = blockIdx.x * 128 + wn * 64 + ni * 8 + tcol;
            float* ac = acc[mi][ni];
            float* p0 = C0 + coff + (size_t)rg * ldc + cg;
            float* p1 = C0 + coff + (size_t)(rg + 8) * ldc + cg;
            *(float2*)p0 = make_float2(ac[0], ac[1]);
            *(float2*)p1 = make_float2(ac[2], ac[3]);
        }
    }
}

// ---------------------------------------------------------------------------
// Flash v3: q-tile 256 rows, 8 warps x 32 q-rows. K/V fragments amortized
// over 2x rows. Register softmax per row pair (identical per-row math).
// Grid (4, 128, 2), 256 threads.
// ---------------------------------------------------------------------------
__global__ __launch_bounds__(256, 1)
void flash_attn(const __half* __restrict__ QKhB, const __half* __restrict__ QKlB,
                const __half* __restrict__ VhB,
                __half* __restrict__ H0B, __half* __restrict__ H1B) {
    extern __shared__ __align__(16) char smem[];
    const unsigned sb = smem_u32(smem);

    const int tid = threadIdx.x, wid = tid >> 5, lane = tid & 31;
    const int sub = lane >> 3, r8 = lane & 7;
    const int trow = lane >> 2, tq2 = (lane & 3) * 2;
    const int qt = blockIdx.x, z = blockIdx.y;
    const int h = z >> 4, b = z & 15;
    const int s = blockIdx.z;

    const __half* QKh = QKhB + (size_t)s * QKSTR;
    const __half* QKl = QKlB + (size_t)s * QKSTR;
    const __half* Vh  = VhB  + (size_t)s * 16777216;
    __half* C0 = H0B + s * 64;
    __half* C1 = H1B + s * 64;

    // Q loads: 256 rows x 64 cols, hi+lo. 8 chunks/thread/matrix.
    {
        const size_t rbase = (size_t)(b << 10) + qt * 256;
#pragma unroll
        for (int i = 0; i < 8; i++) {
            int c = tid + i * 256;
            int r = c >> 3, sc = c & 7;
            unsigned sof = (unsigned)(r * PADK + sc * 8) * 2;
            size_t go = (rbase + r) * 1024 + h * 64 + sc * 8;
            cpasync16(sb + OFF_Q + sof, QKh + go);
            cpasync16(sb + OFF_Q + QBYTES + sof, QKl + go);
        }
    }

#define LOAD_KV(kt, bi)                                                       \
    do {                                                                      \
        unsigned kb = sb + OFF_KV + (bi) * KVBUF;                             \
        _Pragma("unroll")                                                     \
        for (int i_ = 0; i_ < 2; i_++) {                                      \
            int c_ = tid + i_ * 256;                                          \
            int r_ = c_ >> 3, sc_ = c_ & 7;                                   \
            cpasync16(kb + (unsigned)(r_ * PADK + sc_ * 8) * 2,               \
                      QKh + ((size_t)(b << 10) + (kt) * 64 + r_) * 1024 +     \
                          512 + h * 64 + sc_ * 8);                            \
        }                                                                     \
        _Pragma("unroll")                                                     \
        for (int i_ = 0; i_ < 4; i_++) {                                      \
            int c_ = tid + i_ * 256;                                          \
            int r_ = c_ >> 3, sc_ = c_ & 7;                                   \
            cpasync16(kb + 9216 + (unsigned)(r_ * PADK + sc_ * 8) * 2,        \
                      Vh + (size_t)(h * 128 + r_) * 16384 +                   \
                          (size_t)(b << 10) + (kt) * 64 + sc_ * 8);           \
        }                                                                     \
        cp_commit();                                                          \
    } while (0)

    LOAD_KV(0, 0);
    cp_wait0();

    float O[2][16][4];
#pragma unroll
    for (int mf = 0; mf < 2; mf++)
#pragma unroll
        for (int i = 0; i < 16; i++)
#pragma unroll
            for (int j = 0; j < 4; j++) O[mf][i][j] = 0.f;
    float mA[2][2], lA[2][2];
#pragma unroll
    for (int mf = 0; mf < 2; mf++) {
        mA[mf][0] = -1e30f; mA[mf][1] = -1e30f;
        lA[mf][0] = 0.f;    lA[mf][1] = 0.f;
    }

    for (int kt = 0; kt < NKT; kt++) {
        const int bi = kt & 1;
        if (kt) cp_wait0();
        __syncthreads();
        if (kt + 1 < NKT) LOAD_KV(kt + 1, bi ^ 1);

        const unsigned Kb = sb + OFF_KV + bi * KVBUF;
        const unsigned Vb = Kb + 9216;

        // ---- S: 32 rows x 64 keys per warp, 2 terms ----
        float sc[2][8][4];
#pragma unroll
        for (int mf = 0; mf < 2; mf++)
#pragma unroll
            for (int t = 0; t < 8; t++)
#pragma unroll
                for (int j = 0; j < 4; j++) sc[mf][t][j] = 0.f;

#pragma unroll
        for (int ks = 0; ks < 4; ks++) {
            const int k0 = ks * 16;
            unsigned ah[2][4], al[2][4];
#pragma unroll
            for (int mf = 0; mf < 2; mf++) {
                unsigned offa = (unsigned)((wid * 32 + mf * 16 + r8 + (sub & 1) * 8) * PADK +
                                           k0 + (sub >> 1) * 8) * 2;
                ldm4(ah[mf][0], ah[mf][1], ah[mf][2], ah[mf][3], sb + OFF_Q + offa);
                ldm4(al[mf][0], al[mf][1], al[mf][2], al[mf][3],
                     sb + OFF_Q + QBYTES + offa);
            }
            unsigned bk[8][2];
#pragma unroll
            for (int nb = 0; nb < 4; nb++) {
                unsigned offb = (unsigned)((nb * 16 + r8 + (sub >> 1) * 8) * PADK +
                                           k0 + (sub & 1) * 8) * 2;
                unsigned q0, q1, q2, q3;
                ldm4(q0, q1, q2, q3, Kb + offb);
                bk[2 * nb][0] = q0; bk[2 * nb][1] = q1;
                bk[2 * nb + 1][0] = q2; bk[2 * nb + 1][1] = q3;
            }
#pragma unroll
            for (int mf = 0; mf < 2; mf++)
#pragma unroll
                for (int t = 0; t < 8; t++) {
                    mma16816(sc[mf][t], ah[mf], bk[t]);
                    mma16816(sc[mf][t], al[mf], bk[t]);
                }
        }

        // ---- register softmax + P frags, per m-fragment ----
        unsigned pf[2][4][4];
        float fS[2][2];
#pragma unroll
        for (int mf = 0; mf < 2; mf++) {
            float mt0 = sc[mf][0][0], mt1 = sc[mf][0][2];
#pragma unroll
            for (int t = 0; t < 8; t++) {
                mt0 = fmaxf(mt0, fmaxf(sc[mf][t][0], sc[mf][t][1]));
                mt1 = fmaxf(mt1, fmaxf(sc[mf][t][2], sc[mf][t][3]));
            }
            mt0 = fmaxf(mt0, __shfl_xor_sync(~0u, mt0, 1));
            mt0 = fmaxf(mt0, __shfl_xor_sync(~0u, mt0, 2));
            mt1 = fmaxf(mt1, __shfl_xor_sync(~0u, mt1, 1));
            mt1 = fmaxf(mt1, __shfl_xor_sync(~0u, mt1, 2));
            float mn0 = fmaxf(mA[mf][0], mt0), mn1 = fmaxf(mA[mf][1], mt1);
            float f0 = __expf(mA[mf][0] - mn0), f1 = __expf(mA[mf][1] - mn1);
            float sum0 = 0.f, sum1 = 0.f;
#pragma unroll
            for (int kk = 0; kk < 4; kk++) {
                float e00 = __expf(sc[mf][2 * kk][0] - mn0);
                float e01 = __expf(sc[mf][2 * kk][1] - mn0);
                float e02 = __expf(sc[mf][2 * kk][2] - mn1);
                float e03 = __expf(sc[mf][2 * kk][3] - mn1);
                float e10 = __expf(sc[mf][2 * kk + 1][0] - mn0);
                float e11 = __expf(sc[mf][2 * kk + 1][1] - mn0);
                float e12 = __expf(sc[mf][2 * kk + 1][2] - mn1);
                float e13 = __expf(sc[mf][2 * kk + 1][3] - mn1);
                sum0 += e00 + e01 + e10 + e11;
                sum1 += e02 + e03 + e12 + e13;
                pf[mf][kk][0] = h2bits(e00, e01);
                pf[mf][kk][1] = h2bits(e02, e03);
                pf[mf][kk][2] = h2bits(e10, e11);
                pf[mf][kk][3] = h2bits(e12, e13);
            }
            sum0 += __shfl_xor_sync(~0u, sum0, 1);
            sum0 += __shfl_xor_sync(~0u, sum0, 2);
            sum1 += __shfl_xor_sync(~0u, sum1, 1);
            sum1 += __shfl_xor_sync(~0u, sum1, 2);
            lA[mf][0] = lA[mf][0] * f0 + sum0;  mA[mf][0] = mn0;
            lA[mf][1] = lA[mf][1] * f1 + sum1;  mA[mf][1] = mn1;
            fS[mf][0] = f0; fS[mf][1] = f1;
        }

        // ---- rescale O, then PV ----
#pragma unroll
        for (int mf = 0; mf < 2; mf++)
#pragma unroll
            for (int ni = 0; ni < 16; ni++) {
                O[mf][ni][0] *= fS[mf][0]; O[mf][ni][1] *= fS[mf][0];
                O[mf][ni][2] *= fS[mf][1]; O[mf][ni][3] *= fS[mf][1];
            }
#pragma unroll
        for (int kk = 0; kk < 4; kk++) {
            const int k0 = kk * 16;
            unsigned bv[16][2];
#pragma unroll
            for (int nb = 0; nb < 8; nb++) {
                unsigned offv = (unsigned)((nb * 16 + r8 + (sub >> 1) * 8) * PADK +
                                           k0 + (sub & 1) * 8) * 2;
                unsigned q0, q1, q2, q3;
                ldm4(q0, q1, q2, q3, Vb + offv);
                bv[2 * nb][0] = q0; bv[2 * nb][1] = q1;
                bv[2 * nb + 1][0] = q2; bv[2 * nb + 1][1] = q3;
            }
#pragma unroll
            for (int mf = 0; mf < 2; mf++)
#pragma unroll
                for (int ni = 0; ni < 16; ni++)
                    mma16816(O[mf][ni], pf[mf][kk], bv[ni]);
        }
    }
#undef LOAD_KV

    // ---- epilogue ----
    const long long coff = 128LL * h + 1048576LL * b;
#pragma unroll
    for (int mf = 0; mf < 2; mf++) {
        const float inv0 = 1.f / lA[mf][0], inv1 = 1.f / lA[mf][1];
        const int rg0 = qt * 256 + wid * 32 + mf * 16 + trow, rg1 = rg0 + 8;
#pragma unroll
        for (int ni = 0; ni < 16; ni++) {
            int cg = ni * 8 + tq2;
            __half* base = (cg < 64) ? C0 : C1;
            int cl = cg & 63;
            *(__half2*)(base + coff + (size_t)rg0 * 1024 + cl) =
                __floats2half2_rn(O[mf][ni][0] * inv0, O[mf][ni][1] * inv0);
            *(__half2*)(base + coff + (size_t)rg1 * 1024 + cl) =
                __floats2half2_rn(O[mf][ni][2] * inv1, O[mf][ni][3] * inv1);
        }
    }
}

// ---------------------------------------------------------------------------
// Fused prep (R15-proven)
// ---------------------------------------------------------------------------
__global__ void prep_all(const float* __restrict__ Wqn, const float* __restrict__ Wkn,
                         const float* __restrict__ Wqp, const float* __restrict__ Wkp,
                         const float* __restrict__ Wvn, const float* __restrict__ Wvp,
                         const float* __restrict__ Won, const float* __restrict__ Wop,
                         const float* __restrict__ Xn, const float* __restrict__ Xp,
                         __half* __restrict__ Wqkh, __half* __restrict__ Wqkl,
                         __half* __restrict__ Wvh, __half* __restrict__ Woh,
                         __half* __restrict__ Yh, __half* __restrict__ Yl) {
    int bid = blockIdx.x;
    if (bid < 12288) {
        int task = bid >> 11;
        int idx = (bid & 2047) * 256 + threadIdx.x;
        if (idx >= 524288) return;
        int st = task & 1;
        if (task < 2) {
            const float* Wq = st ? Wqp : Wqn;
            const float* Wk = st ? Wkp : Wkn;
            int j = idx >> 9, d = idx & 511;
            int jj = j & 511;
            float v;
            if (j < 512)
                v = Wq[((size_t)((jj >> 6) * 512 + d)) * 64 + (jj & 63)] * 0.125f;
            else
                v = Wk[((size_t)((jj >> 6) * 512 + d)) * 64 + (jj & 63)];
            __half h = __float2half_rn(v);
            Wqkh[(size_t)st * WSTR + idx] = h;
            Wqkl[(size_t)st * WSTR + idx] = __float2half_rn(v - __half2float(h));
        } else if (task < 4) {
            const float* Wv = st ? Wvp : Wvn;
            int j = idx >> 9, d = idx & 511;
            Wvh[(size_t)st * WSTR + idx] =
                __float2half_rn(Wv[((size_t)((j >> 6) * 512 + d)) * 64 + (j & 63)]);
        } else {
            const float* Wo = st ? Wop : Won;
            int e = idx >> 10, j = idx & 1023;
            Woh[(size_t)st * WSTR + idx] = __float2half_rn(Wo[(size_t)j * 512 + e]);
        }
    } else {
        int r = bid - 12288;
        int st = r >> 13;
        int i = (r & 8191) * 256 + threadIdx.x;
        if (i >= ROWS * 512 / 4) return;
        const float* X = st ? Xp : Xn;
        float4 v = ((const float4*)X)[i];
        __half2 h0, l0a, h1, l1a;
        split2(v.x, v.y, h0, l0a);
        split2(v.z, v.w, h1, l1a);
        uint2 uh, ul;
        uh.x = *reinterpret_cast<unsigned*>(&h0);
        uh.y = *reinterpret_cast<unsigned*>(&h1);
        ul.x = *reinterpret_cast<unsigned*>(&l0a);
        ul.y = *reinterpret_cast<unsigned*>(&l1a);
        ((uint2*)(Yh + (size_t)st * XSTR))[i] = uh;
        ((uint2*)(Yl + (size_t)st * XSTR))[i] = ul;
    }
}

// ---------------------------------------------------------------------------
// Host launcher: 4 kernel launches
// ---------------------------------------------------------------------------
extern "C" void kernel_launch(void* const* d_in, const int* in_sizes, int n_in,
                              void* d_out, int out_size) {
    const float* Xn  = (const float*)d_in[0];
    const float* Xp  = (const float*)d_in[1];
    const float* Wqn = (const float*)d_in[2];
    const float* Wqp = (const float*)d_in[3];
    const float* Wkn = (const float*)d_in[4];
    const float* Wkp = (const float*)d_in[5];
    const float* Wvn = (const float*)d_in[6];
    const float* Wvp = (const float*)d_in[7];
    const float* Won = (const float*)d_in[8];
    const float* Wop = (const float*)d_in[9];
    float* out = (float*)d_out;

    __half *Wqkh, *Wqkl, *Wvh, *Woh, *Xh, *Xl, *QKh, *QKl, *Vth, *H;
    cudaGetSymbolAddress((void**)&Wqkh, g_Wqkh);
    cudaGetSymbolAddress((void**)&Wqkl, g_Wqkl);
    cudaGetSymbolAddress((void**)&Wvh,  g_Wvh);
    cudaGetSymbolAddress((void**)&Woh,  g_Woh);
    cudaGetSymbolAddress((void**)&Xh,   g_Xh);
    cudaGetSymbolAddress((void**)&Xl,   g_Xl);
    cudaGetSymbolAddress((void**)&QKh,  g_QKh);
    cudaGetSymbolAddress((void**)&QKl,  g_QKl);
    cudaGetSymbolAddress((void**)&Vth,  g_Vth);
    cudaGetSymbolAddress((void**)&H,    g_H);

    cudaFuncSetAttribute(hgemm23, cudaFuncAttributeMaxDynamicSharedMemorySize,
                         GEMM_SMEM);
    cudaFuncSetAttribute(hgemm, cudaFuncAttributeMaxDynamicSharedMemorySize,
                         GEMM_SMEM);
    cudaFuncSetAttribute(flash_attn, cudaFuncAttributeMaxDynamicSharedMemorySize,
                         FA_SMEM);

    // 1) fused prep (weights + inputs)
    prep_all<<<28672, 256>>>(Wqn, Wkn, Wqp, Wkp, Wvn, Wvp, Won, Wop, Xn, Xp,
                             Wqkh, Wqkl, Wvh, Woh, Xh, Xl);

    // 2) fused QK-proj + V-proj, both streams
    hgemm23<<<4096, 128, GEMM_SMEM>>>(Xh, Xl, Wqkh, Wqkl, Wvh, QKh, QKl, Vth);

    // 3) flash attention v3 (256-row q-tiles), both streams (z)
    flash_attn<<<dim3(4, 128, 2), 256, FA_SMEM>>>(
        QKh, QKl, Vth, H, H + QKSTR);

    // 4) output projections, fp32 out, both streams (z)
    hgemm<<<dim3(4, 128, 2), 128, GEMM_SMEM>>>(
        H, HSTR, 1024, Woh, WSTR, 1024, out, OSTR, 512, 1024);
}